// round 8
// baseline (speedup 1.0000x reference)
#include <cuda_runtime.h>
#include <cstdint>

#define TN 2048
#define BN 256
#define DN 40
#define HN 128
#define CN 35
#define TDN (TN * DN)
#define NCTA 128
#define NTHR 512

// ---------------------------------------------------------------------------
// Persistent device scratch.
__device__ __align__(16) float g_xT[TDN * BN];     // x transposed: [t*D + d][b]
__device__ __align__(16) float g_h0[4][HN * BN];   // layer0 h, depth-4, [k][b]
__device__ __align__(16) float g_h1[2][HN * BN];   // layer1 h, depth-2, [k][b]

struct alignas(128) BarSlot { unsigned v; };
__device__ BarSlot g_cnt;                          // full-grid barrier (rare)
__device__ volatile BarSlot g_phz;
__device__ __align__(128) unsigned g_gflag[4][2][16];  // [group][layer][ctaIdx]

// ---------------------------------------------------------------------------
union F2U { float2 f; unsigned long long u; };
__device__ __forceinline__ void ffma2(float2& acc, float2 a, float2 b) {
    F2U ua, ub, uc;
    ua.f = a; ub.f = b; uc.f = acc;
    asm("fma.rn.f32x2 %0, %1, %2, %0;" : "+l"(uc.u) : "l"(ua.u), "l"(ub.u));
    acc = uc.f;
}
__device__ __forceinline__ float sigf(float x)  { return 1.0f / (1.0f + __expf(-x)); }
__device__ __forceinline__ float tanhx(float x) {
    x = fminf(fmaxf(x, -15.f), 15.f);
    float e = __expf(2.f * x);
    return (e - 1.f) / (e + 1.f);
}

__device__ __forceinline__ unsigned ldacq(const unsigned* p) {
    unsigned v;
    asm volatile("ld.acquire.gpu.global.u32 %0, [%1];" : "=r"(v) : "l"(p) : "memory");
    return v;
}
__device__ __forceinline__ void strel(unsigned* p, unsigned v) {
    asm volatile("st.release.gpu.global.u32 [%0], %1;" :: "l"(p), "r"(v) : "memory");
}

// Full-grid barrier (used twice per launch; monotonic phase, no re-init).
__device__ __forceinline__ void gbar_full() {
    __syncthreads();
    if (threadIdx.x == 0) {
        unsigned ph = g_phz.v;
        __threadfence();
        if (atomicAdd(&g_cnt.v, 1u) == NCTA - 1u) {
            g_cnt.v = 0u;
            __threadfence();
            g_phz.v = ph + 1u;
        } else {
            while (g_phz.v == ph) { }
            __threadfence();
        }
    }
    __syncthreads();
}

// ---------------------------------------------------------------------------
// SMEM (~152.3 KB dynamic).
struct SmemLayout {
    float2 wB[8][4][HN];      // W_ih rows, dup {w,w}   (32 KB)
    float2 wA[8][4][HN];      // W_hh rows, dup {w,w}   (32 KB)
    float2 sbd[8][4];         // bias dup
    float  sin1[HN * 64];     // staged input 1 [k][64] (32 KB)
    float  sin2[HN * 64];     // staged input 2 [k][64] (32 KB)
    float2 red2[3][128][8];   // k-split partials        (24 KB)
};
#define SMEM_BYTES ((int)sizeof(SmemLayout))

struct LstmArgs {
    const float *x;
    const int   *length;
    const float *Wih0, *Whh0, *bih0, *bhh0;
    const float *Wih1, *Whh1, *bih1, *bhh1;
    const float *lng, *lnb, *fcw, *fcb;
    float       *out;
};

// Stage `rows` x 64 floats from src (row stride BN, column offset bbase).
__device__ __forceinline__ void stage_tile(float* dst, const float* src,
                                           int rows, int bbase, int tid) {
    int total = rows * 16;  // float4s
    for (int i = tid; i < total; i += NTHR) {
        int r = i >> 4, j = (i & 15) << 2;
        float4 v = __ldcg((const float4*)(src + (size_t)r * BN + bbase + j));
        *(float4*)(dst + r * 64 + j) = v;
    }
}

// MAC over k range [kbeg, kend) for one unit-pair against staged input.
__device__ __forceinline__ void mac_range(
    float2 acc0[4], float2 acc1[4],
    const float2 (*w)[4][HN], int lu0,
    const float* sv, int kbeg, int kend)
{
#pragma unroll 2
    for (int k4 = kbeg; k4 < kend; k4 += 4) {
        float2 v0 = *(const float2*)(sv + (k4 + 0) * 64);
        float2 v1 = *(const float2*)(sv + (k4 + 1) * 64);
        float2 v2 = *(const float2*)(sv + (k4 + 2) * 64);
        float2 v3 = *(const float2*)(sv + (k4 + 3) * 64);
#pragma unroll
        for (int g = 0; g < 4; g++) {
            float4 wa = *(const float4*)&w[lu0][g][k4];
            float4 wb = *(const float4*)&w[lu0][g][k4 + 2];
            ffma2(acc0[g], make_float2(wa.x, wa.y), v0);
            ffma2(acc0[g], make_float2(wa.z, wa.w), v1);
            ffma2(acc0[g], make_float2(wb.x, wb.y), v2);
            ffma2(acc0[g], make_float2(wb.z, wb.w), v3);
        }
#pragma unroll
        for (int g = 0; g < 4; g++) {
            float4 wa = *(const float4*)&w[lu0 + 1][g][k4];
            float4 wb = *(const float4*)&w[lu0 + 1][g][k4 + 2];
            ffma2(acc1[g], make_float2(wa.x, wa.y), v0);
            ffma2(acc1[g], make_float2(wa.z, wa.w), v1);
            ffma2(acc1[g], make_float2(wb.x, wb.y), v2);
            ffma2(acc1[g], make_float2(wb.z, wb.w), v3);
        }
    }
}

// ---------------------------------------------------------------------------
// Per-layer step loop. CTA = 8 units x 64 batch, 512 threads (16 warps).
// Warp (wp, ks): wp in 0..3 -> unit pair; ks in 0..3 -> k-quarter.
// ks>0 warps write partials to SMEM; ks=0 warps reduce + activations + store.
template <int LAYER>
__device__ void run_layer(const LstmArgs& a, SmemLayout* sm,
                          int u0, int bbase, int grp, int gidx)
{
    constexpr int K1 = LAYER ? HN : DN;
    const int tid  = threadIdx.x;
    const int wid  = tid >> 5;
    const int lane = tid & 31;
    const int ks   = wid & 3;
    const int wp   = wid >> 2;
    const int lu0  = wp * 2;
    const int b0   = 2 * lane;
    const int gu0  = u0 + lu0;
    const int ridx = wp * 32 + lane;

    // k-quarter bounds (layer0 in1: {0,12,24,32,40})
    const int kb1 = LAYER ? (ks * 32) : ((ks == 0) ? 0 : (ks == 1) ? 12 : (ks == 2) ? 24 : 32);
    const int ke1 = LAYER ? (ks * 32 + 32) : ((ks == 0) ? 12 : (ks == 1) ? 24 : (ks == 2) ? 32 : 40);
    const int kb2 = ks * 32, ke2 = kb2 + 32;

    const float* Wih = LAYER ? a.Wih1 : a.Wih0;
    const float* Whh = LAYER ? a.Whh1 : a.Whh0;
    const float* bih = LAYER ? a.bih1 : a.bih0;
    const float* bhh = LAYER ? a.bhh1 : a.bhh0;

    // ---- stage duplicated weights + bias (once) ----
    for (int i = tid; i < 32 * K1; i += NTHR) {
        int r = i / K1, k = i - r * K1;
        int uu = r >> 2, g = r & 3;
        float w = Wih[(size_t)(g * HN + u0 + uu) * K1 + k];
        sm->wB[uu][g][k] = make_float2(w, w);
    }
    for (int i = tid; i < 32 * HN; i += NTHR) {
        int r = i >> 7, k = i & 127;
        int uu = r >> 2, g = r & 3;
        float w = Whh[(size_t)(g * HN + u0 + uu) * HN + k];
        sm->wA[uu][g][k] = make_float2(w, w);
    }
    if (tid < 32) {
        int uu = tid >> 2, g = tid & 3;
        float b = bih[g * HN + u0 + uu] + bhh[g * HN + u0 + uu];
        sm->sbd[uu][g] = make_float2(b, b);
    }

    const int len0 = a.length[bbase + b0];
    const int len1 = a.length[bbase + b0 + 1];

    unsigned* ownF = &g_gflag[grp][LAYER][0];
    unsigned* othF = &g_gflag[grp][1 - LAYER][0];
    const unsigned fbase = *(volatile unsigned*)&ownF[0];  // group-uniform

    float cA0 = 0.f, cB0 = 0.f, hA0 = 0.f, hB0 = 0.f;
    float cA1 = 0.f, cB1 = 0.f, hA1 = 0.f, hB1 = 0.f;
    __syncthreads();

#pragma unroll 1
    for (int it = 0; it <= TN; it++) {
        const int  t      = LAYER ? it - 1 : it;
        const bool active = LAYER ? (it >= 1) : (it < TN);
        if (active) {
            const float* in1  = LAYER ? g_h0[t & 3]
                                      : (g_xT + (size_t)t * DN * BN);
            const float* in2  = LAYER ? g_h1[(t + 1) & 1] : g_h0[(t + 3) & 3];
            float*       hout = LAYER ? g_h1[t & 1]       : g_h0[t & 3];

            if (!LAYER)   // x is static: stage before any waiting
                stage_tile(sm->sin1, in1, K1, bbase, tid);

            // ---- flag waits (parallel per-lane acquire polls) ----
            if (tid < 16) {
                unsigned tgt = fbase + (unsigned)it;   // own layer: peers done it-1
                while (ldacq(&ownF[tid]) < tgt) { }
            } else if (tid < 32) {
                unsigned tgt = LAYER ? (fbase + (unsigned)it)               // h0[t] ready
                                     : (it >= 2 ? fbase + (unsigned)(it - 2)
                                                : fbase);                   // lazy reuse
                while (ldacq(&othF[tid - 16]) < tgt) { }
            }
            __syncthreads();

            if (LAYER)
                stage_tile(sm->sin1, in1, K1, bbase, tid);
            stage_tile(sm->sin2, in2, HN, bbase, tid);
            __syncthreads();

            float2 acc0[4], acc1[4];
            if (ks == 0) {
#pragma unroll
                for (int g = 0; g < 4; g++) {
                    acc0[g] = sm->sbd[lu0][g];
                    acc1[g] = sm->sbd[lu0 + 1][g];
                }
            } else {
#pragma unroll
                for (int g = 0; g < 4; g++) {
                    acc0[g] = make_float2(0.f, 0.f);
                    acc1[g] = make_float2(0.f, 0.f);
                }
            }

            mac_range(acc0, acc1, sm->wB, lu0, sm->sin1 + b0, kb1, ke1);
            mac_range(acc0, acc1, sm->wA, lu0, sm->sin2 + b0, kb2, ke2);

            if (ks != 0) {
#pragma unroll
                for (int g = 0; g < 4; g++) {
                    sm->red2[ks - 1][ridx][g]     = acc0[g];
                    sm->red2[ks - 1][ridx][g + 4] = acc1[g];
                }
            }
            __syncthreads();
            if (ks == 0) {
#pragma unroll
                for (int s = 0; s < 3; s++) {
#pragma unroll
                    for (int g = 0; g < 4; g++) {
                        float2 p0 = sm->red2[s][ridx][g];
                        float2 p1 = sm->red2[s][ridx][g + 4];
                        acc0[g].x += p0.x; acc0[g].y += p0.y;
                        acc1[g].x += p1.x; acc1[g].y += p1.y;
                    }
                }
                // gates -> state (freeze for t >= length)
                {
                    float i_ = sigf(acc0[0].x), f_ = sigf(acc0[1].x);
                    float g_ = tanhx(acc0[2].x), o_ = sigf(acc0[3].x);
                    float cn = f_ * cA0 + i_ * g_;
                    float hn = o_ * tanhx(cn);
                    if (t < len0) { cA0 = cn; hA0 = hn; }
                }
                {
                    float i_ = sigf(acc0[0].y), f_ = sigf(acc0[1].y);
                    float g_ = tanhx(acc0[2].y), o_ = sigf(acc0[3].y);
                    float cn = f_ * cB0 + i_ * g_;
                    float hn = o_ * tanhx(cn);
                    if (t < len1) { cB0 = cn; hB0 = hn; }
                }
                {
                    float i_ = sigf(acc1[0].x), f_ = sigf(acc1[1].x);
                    float g_ = tanhx(acc1[2].x), o_ = sigf(acc1[3].x);
                    float cn = f_ * cA1 + i_ * g_;
                    float hn = o_ * tanhx(cn);
                    if (t < len0) { cA1 = cn; hA1 = hn; }
                }
                {
                    float i_ = sigf(acc1[0].y), f_ = sigf(acc1[1].y);
                    float g_ = tanhx(acc1[2].y), o_ = sigf(acc1[3].y);
                    float cn = f_ * cB1 + i_ * g_;
                    float hn = o_ * tanhx(cn);
                    if (t < len1) { cB1 = cn; hB1 = hn; }
                }
                __stcg((float2*)&hout[(size_t)gu0 * BN + bbase + b0],
                       make_float2(hA0, hB0));
                __stcg((float2*)&hout[(size_t)(gu0 + 1) * BN + bbase + b0],
                       make_float2(hA1, hB1));
            }
            __syncthreads();   // h stores complete CTA-wide
        }
        if (tid == 0) strel(&ownF[gidx], fbase + (unsigned)(it + 1));
    }
}

// ---------------------------------------------------------------------------
// Single persistent kernel: transpose + zero, 2049 steps, LN+FC head.
__global__ void __launch_bounds__(NTHR, 1) lstm_kernel(LstmArgs a) {
    extern __shared__ char smem_raw[];
    SmemLayout* sm = (SmemLayout*)smem_raw;
    const int bid = blockIdx.x;
    const int tid = threadIdx.x;

    // ---- phase 0: transpose x into g_xT + zero h buffers ----
    {
        float (*tile)[33] = (float(*)[33])sm->sin1;  // 32x33 scratch
        const int tx = tid & 31, ty = tid >> 5;      // 32 x 16
        const int ntile = (TDN / 32) * (BN / 32);    // 20480
        for (int tl = bid; tl < ntile; tl += NCTA) {
            int tdBase = (tl % (TDN / 32)) * 32;
            int bBase  = (tl / (TDN / 32)) * 32;
#pragma unroll
            for (int j = 0; j < 2; j++)
                tile[ty + j * 16][tx] =
                    a.x[(size_t)(bBase + ty + j * 16) * TDN + tdBase + tx];
            __syncthreads();
#pragma unroll
            for (int j = 0; j < 2; j++)
                g_xT[(size_t)(tdBase + ty + j * 16) * BN + bBase + tx] =
                    tile[tx][ty + j * 16];
            __syncthreads();
        }
        for (int i = bid * NTHR + tid; i < HN * BN; i += NCTA * NTHR) {
            g_h0[0][i] = 0.f; g_h0[1][i] = 0.f;
            g_h0[2][i] = 0.f; g_h0[3][i] = 0.f;
            g_h1[0][i] = 0.f; g_h1[1][i] = 0.f;
        }
    }
    gbar_full();

    // ---- phase 1: step loop (layer-split, flag-decoupled sync) ----
    const int blk   = bid & 63;
    const int u0    = (blk >> 2) * 8;
    const int grp   = blk & 3;
    const int bbase = grp * 64;
    const int gidx  = blk >> 2;    // 0..15 within (group, layer)
    if (bid < 64) run_layer<0>(a, sm, u0, bbase, grp, gidx);
    else          run_layer<1>(a, sm, u0, bbase, grp, gidx);

    gbar_full();

    // ---- phase 2: LN + FC head (2 batch rows per CTA) ----
    {
        float* hv  = sm->sin1;
        float* red = sm->sin1 + 160;
        const int idx = ((bid >> 6) << 4) | ((bid >> 2) & 15);  // 0..31 in group
        const int brow = bbase + idx * 2;

        for (int rep = 0; rep < 2; rep++) {
            int b = brow + rep;
            float v = (tid < HN)
                ? __ldcg(&g_h1[(TN - 1) & 1][(size_t)tid * BN + b]) : 0.f;

            float s = v;
#pragma unroll
            for (int o = 16; o; o >>= 1) s += __shfl_xor_sync(0xffffffffu, s, o);
            if ((tid & 31) == 0 && tid < HN) red[tid >> 5] = s;
            __syncthreads();
            float mu = (red[0] + red[1] + red[2] + red[3]) * (1.0f / HN);

            float d = (tid < HN) ? (v - mu) : 0.f;
            float q = d * d;
#pragma unroll
            for (int o = 16; o; o >>= 1) q += __shfl_xor_sync(0xffffffffu, q, o);
            __syncthreads();
            if ((tid & 31) == 0 && tid < HN) red[tid >> 5] = q;
            __syncthreads();
            float var = (red[0] + red[1] + red[2] + red[3]) * (1.0f / HN);

            if (tid < HN)
                hv[tid] = d * rsqrtf(var + 1e-5f) * a.lng[tid] + a.lnb[tid];
            __syncthreads();

            if (tid < CN) {
                float acc = a.fcb[tid];
#pragma unroll 4
                for (int h = 0; h < HN; h++)
                    acc = fmaf(hv[h], a.fcw[tid * HN + h], acc);
                a.out[b * CN + tid] = acc;
            }
            __syncthreads();
        }
    }
}

// ---------------------------------------------------------------------------
extern "C" void kernel_launch(void* const* d_in, const int* in_sizes, int n_in,
                              void* d_out, int out_size)
{
    LstmArgs a;
    a.x      = (const float*)d_in[0];
    a.length = (const int*)  d_in[1];
    a.Wih0 = (const float*)d_in[2];
    a.Whh0 = (const float*)d_in[3];
    a.bih0 = (const float*)d_in[4];
    a.bhh0 = (const float*)d_in[5];
    a.Wih1 = (const float*)d_in[6];
    a.Whh1 = (const float*)d_in[7];
    a.bih1 = (const float*)d_in[8];
    a.bhh1 = (const float*)d_in[9];
    a.lng  = (const float*)d_in[10];
    a.lnb  = (const float*)d_in[11];
    a.fcw  = (const float*)d_in[12];
    a.fcb  = (const float*)d_in[13];
    a.out  = (float*)d_out;

    static bool attr_done = false;
    if (!attr_done) {
        cudaFuncSetAttribute(lstm_kernel,
                             cudaFuncAttributeMaxDynamicSharedMemorySize,
                             SMEM_BYTES);
        attr_done = true;
    }

    lstm_kernel<<<NCTA, NTHR, SMEM_BYTES>>>(a);
}

// round 9
// speedup vs baseline: 1.4967x; 1.4967x over previous
#include <cuda_runtime.h>
#include <cstdint>

#define TN 2048
#define BN 256
#define DN 40
#define HN 128
#define CN 35
#define TDN (TN * DN)
#define NCTA 128
#define NTHR 256

// ---------------------------------------------------------------------------
// Persistent device scratch.
__device__ __align__(16) float g_xT[TDN * BN];     // x transposed: [t*D + d][b]
__device__ __align__(16) float g_h0[2][HN * BN];   // layer0 h double buffer, [k][b]
__device__ __align__(16) float g_h1[2][HN * BN];   // layer1 h double buffer, [k][b]

struct alignas(128) BarSlot { unsigned v; };
__device__ BarSlot g_cnt;                          // full-grid barrier (rare)
__device__ volatile BarSlot g_phz;                 // monotonic phase
__device__ __align__(128) unsigned g_flag[4][32];  // [group][ublock] step counters

// ---------------------------------------------------------------------------
union F2U { float2 f; unsigned long long u; };
__device__ __forceinline__ void ffma2(float2& acc, float2 a, float2 b) {
    F2U ua, ub, uc;
    ua.f = a; ub.f = b; uc.f = acc;
    asm("fma.rn.f32x2 %0, %1, %2, %0;" : "+l"(uc.u) : "l"(ua.u), "l"(ub.u));
    acc = uc.f;
}
__device__ __forceinline__ float sigf(float x)  { return 1.0f / (1.0f + __expf(-x)); }
__device__ __forceinline__ float tanhx(float x) {
    x = fminf(fmaxf(x, -15.f), 15.f);
    float e = __expf(2.f * x);
    return (e - 1.f) / (e + 1.f);
}
__device__ __forceinline__ unsigned ldacq(const unsigned* p) {
    unsigned v;
    asm volatile("ld.acquire.gpu.global.u32 %0, [%1];" : "=r"(v) : "l"(p) : "memory");
    return v;
}
__device__ __forceinline__ void strel(unsigned* p, unsigned v) {
    asm volatile("st.release.gpu.global.u32 [%0], %1;" :: "l"(p), "r"(v) : "memory");
}

// Full-grid barrier (twice per launch; monotonic phase, works across replays).
__device__ __forceinline__ void gbar_full() {
    __syncthreads();
    if (threadIdx.x == 0) {
        unsigned ph = g_phz.v;
        __threadfence();
        if (atomicAdd(&g_cnt.v, 1u) == NCTA - 1u) {
            g_cnt.v = 0u;
            __threadfence();
            g_phz.v = ph + 1u;
        } else {
            while (g_phz.v == ph) { }
            __threadfence();
        }
    }
    __syncthreads();
}

// ---------------------------------------------------------------------------
// SMEM (~109 KB dynamic). Weights gate-pair packed: w[u][k][gp] = {w_g0, w_g1}.
struct alignas(16) SmemLayout {
    float2 wx [4][DN][2];    // L0 W_ih  (2.5 KB)
    float2 wh0[4][HN][2];    // L0 W_hh  (8 KB)
    float2 w1i[4][HN][2];    // L1 W_ih  (8 KB)
    float2 w1h[4][HN][2];    // L1 W_hh  (8 KB)
    float2 sb[2][4][2];      // bias pairs per stream/unit
    float  sx [DN * 64];     // staged x tile        (10 KB)
    float  sh0[HN * 64];     // staged h0(it-1) tile (32 KB) — used by BOTH streams
    float  sh1[HN * 64];     // staged h1(it-2) tile (32 KB)
    float2 red[4][32][8];    // k-half partials       (8 KB)
};
#define SMEM_BYTES ((int)sizeof(SmemLayout))

struct LstmArgs {
    const float *x;
    const int   *length;
    const float *Wih0, *Whh0, *bih0, *bhh0;
    const float *Wih1, *Whh1, *bih1, *bhh1;
    const float *lng, *lnb, *fcw, *fcb;
    float       *out;
};

// MAC over k range for 2 units; gate-pair FFMA2 packing.
__device__ __forceinline__ void mac_seg(
    float2 acc0[4], float2 acc1[4],
    const float4* __restrict__ w0, const float4* __restrict__ w1,
    const float* __restrict__ sv, int kb, int ke)
{
#pragma unroll 4
    for (int k = kb; k < ke; k++) {
        float2 v  = *(const float2*)(sv + (k << 6));
        float2 d0 = make_float2(v.x, v.x);
        float2 d1 = make_float2(v.y, v.y);
        float4 wa = w0[k];   // {Wi, Wf, Wg, Wo} of unit 0
        ffma2(acc0[0], make_float2(wa.x, wa.y), d0);
        ffma2(acc0[1], make_float2(wa.z, wa.w), d0);
        ffma2(acc0[2], make_float2(wa.x, wa.y), d1);
        ffma2(acc0[3], make_float2(wa.z, wa.w), d1);
        float4 wb = w1[k];   // unit 1
        ffma2(acc1[0], make_float2(wb.x, wb.y), d0);
        ffma2(acc1[1], make_float2(wb.z, wb.w), d0);
        ffma2(acc1[2], make_float2(wb.x, wb.y), d1);
        ffma2(acc1[3], make_float2(wb.z, wb.w), d1);
    }
}

// ---------------------------------------------------------------------------
// Single persistent kernel.
__global__ void __launch_bounds__(NTHR, 1) lstm_kernel(LstmArgs a) {
    extern __shared__ char smem_raw[];
    SmemLayout* sm = (SmemLayout*)smem_raw;
    const int bid = blockIdx.x;
    const int tid = threadIdx.x;

    const int ub    = bid >> 2;       // 0..31 : unit block (4 units)
    const int grp   = bid & 3;        // 0..3  : batch group (64)
    const int u0    = ub * 4;
    const int bbase = grp * 64;

    // ---- phase 0: transpose x, zero state, zero flags, pack weights ----
    {
        float (*tile)[33] = (float(*)[33])sm->sh0;
        const int tx = tid & 31, ty = tid >> 5;   // 32 x 8
        const int ntile = (TDN / 32) * (BN / 32); // 20480
        for (int tl = bid; tl < ntile; tl += NCTA) {
            int tdBase = (tl % (TDN / 32)) * 32;
            int bBase  = (tl / (TDN / 32)) * 32;
#pragma unroll
            for (int j = 0; j < 4; j++)
                tile[ty + j * 8][tx] =
                    a.x[(size_t)(bBase + ty + j * 8) * TDN + tdBase + tx];
            __syncthreads();
#pragma unroll
            for (int j = 0; j < 4; j++)
                g_xT[(size_t)(tdBase + ty + j * 8) * BN + bBase + tx] =
                    tile[tx][ty + j * 8];
            __syncthreads();
        }
        for (int i = bid * NTHR + tid; i < HN * BN; i += NCTA * NTHR) {
            g_h0[0][i] = 0.f; g_h0[1][i] = 0.f;
            g_h1[0][i] = 0.f; g_h1[1][i] = 0.f;
        }
        if (bid == 0 && tid < 128)
            *(volatile unsigned*)&g_flag[tid >> 5][tid & 31] = 0u;

        // weight packing (one-time)
        for (int i = tid; i < 4 * DN; i += NTHR) {
            int u = i / DN, k = i - u * DN, r = u0 + u;
            sm->wx[u][k][0] = make_float2(a.Wih0[(0 * HN + r) * DN + k],
                                          a.Wih0[(1 * HN + r) * DN + k]);
            sm->wx[u][k][1] = make_float2(a.Wih0[(2 * HN + r) * DN + k],
                                          a.Wih0[(3 * HN + r) * DN + k]);
        }
        for (int i = tid; i < 4 * HN; i += NTHR) {
            int u = i >> 7, k = i & 127, r = u0 + u;
            sm->wh0[u][k][0] = make_float2(a.Whh0[(0 * HN + r) * HN + k],
                                           a.Whh0[(1 * HN + r) * HN + k]);
            sm->wh0[u][k][1] = make_float2(a.Whh0[(2 * HN + r) * HN + k],
                                           a.Whh0[(3 * HN + r) * HN + k]);
            sm->w1i[u][k][0] = make_float2(a.Wih1[(0 * HN + r) * HN + k],
                                           a.Wih1[(1 * HN + r) * HN + k]);
            sm->w1i[u][k][1] = make_float2(a.Wih1[(2 * HN + r) * HN + k],
                                           a.Wih1[(3 * HN + r) * HN + k]);
            sm->w1h[u][k][0] = make_float2(a.Whh1[(0 * HN + r) * HN + k],
                                           a.Whh1[(1 * HN + r) * HN + k]);
            sm->w1h[u][k][1] = make_float2(a.Whh1[(2 * HN + r) * HN + k],
                                           a.Whh1[(3 * HN + r) * HN + k]);
        }
        if (tid < 16) {
            int s = tid >> 3, u = (tid >> 1) & 3, gp = tid & 1, r = u0 + u;
            const float* bi = s ? a.bih1 : a.bih0;
            const float* bh = s ? a.bhh1 : a.bhh0;
            int g0 = gp * 2, g1 = gp * 2 + 1;
            sm->sb[s][u][gp] = make_float2(bi[g0 * HN + r] + bh[g0 * HN + r],
                                           bi[g1 * HN + r] + bh[g1 * HN + r]);
        }
    }
    gbar_full();

    // ---- phase 1: fused 2-layer step loop, one group barrier per step ----
    {
        const int wid  = tid >> 5;
        const int lane = tid & 31;
        const int s    = wid >> 2;          // 0: layer0, 1: layer1
        const int up   = (wid >> 1) & 1;    // unit pair
        const int kh   = wid & 1;           // k-half
        const int lu0  = up * 2;
        const int b0   = 2 * lane;
        const int ridx = s * 2 + up;

        const int len0 = a.length[bbase + b0];
        const int len1 = a.length[bbase + b0 + 1];

        const float4* wp1u0 = s ? (const float4*)&sm->w1i[lu0][0][0]
                                : (const float4*)&sm->wx [lu0][0][0];
        const float4* wp1u1 = s ? (const float4*)&sm->w1i[lu0 + 1][0][0]
                                : (const float4*)&sm->wx [lu0 + 1][0][0];
        const float4* wp2u0 = s ? (const float4*)&sm->w1h[lu0][0][0]
                                : (const float4*)&sm->wh0[lu0][0][0];
        const float4* wp2u1 = s ? (const float4*)&sm->w1h[lu0 + 1][0][0]
                                : (const float4*)&sm->wh0[lu0 + 1][0][0];
        const float* in1base = s ? sm->sh0 : sm->sx;   // part-1 input tile
        const int kb1 = s ? (kh * 64) : (kh * 20);
        const int ke1 = s ? (kh * 64 + 64) : (kh * 20 + 20);
        const int kb2 = kh * 64, ke2 = kb2 + 64;

        // register state (ks0 warps only): c/h for 2 units x 2 batch rows
        float c00 = 0.f, c01 = 0.f, c10 = 0.f, c11 = 0.f;
        float h00 = 0.f, h01 = 0.f, h10 = 0.f, h11 = 0.f;

#pragma unroll 1
        for (int it = 0; it <= TN; it++) {
            // stage x tile (static input, overlaps the flag poll below)
            if (it < TN) {
                const float* xsrc = g_xT + (size_t)it * DN * BN + bbase;
                for (int i = tid; i < DN * 16; i += NTHR) {
                    int r = i >> 4, j = (i & 15) << 2;
                    *(float4*)(sm->sx + r * 64 + j) =
                        __ldcg((const float4*)(xsrc + (size_t)r * BN + j));
                }
            }
            // wait: all 32 ublock CTAs of this group published superstep it-1
            if (tid < 32)
                while (ldacq(&g_flag[grp][tid]) < (unsigned)it) { }
            __syncthreads();

            // stage h0(it-1) [shared by both streams] and h1(it-2)
            {
                const float* s0 = g_h0[(it + 1) & 1] + bbase;
                const float* s1 = g_h1[it & 1] + bbase;
                for (int i = tid; i < HN * 16; i += NTHR) {
                    int r = i >> 4, j = (i & 15) << 2;
                    *(float4*)(sm->sh0 + r * 64 + j) =
                        __ldcg((const float4*)(s0 + (size_t)r * BN + j));
                    *(float4*)(sm->sh1 + r * 64 + j) =
                        __ldcg((const float4*)(s1 + (size_t)r * BN + j));
                }
            }
            __syncthreads();

            const bool active = s ? (it >= 1) : (it < TN);
            float2 acc0[4], acc1[4];
            if (active) {
                if (kh == 0) {
#pragma unroll
                    for (int j = 0; j < 4; j++) {
                        float2 b = sm->sb[s][lu0][j & 1];
                        acc0[j] = b;
                        float2 b2 = sm->sb[s][lu0 + 1][j & 1];
                        acc1[j] = b2;
                    }
                } else {
#pragma unroll
                    for (int j = 0; j < 4; j++) {
                        acc0[j] = make_float2(0.f, 0.f);
                        acc1[j] = make_float2(0.f, 0.f);
                    }
                }
                mac_seg(acc0, acc1, wp1u0, wp1u1, in1base + b0, kb1, ke1);
                mac_seg(acc0, acc1, wp2u0, wp2u1,
                        (s ? sm->sh1 : sm->sh0) + b0, kb2, ke2);
                if (kh == 1) {
#pragma unroll
                    for (int j = 0; j < 4; j++) {
                        sm->red[ridx][lane][j]     = acc0[j];
                        sm->red[ridx][lane][j + 4] = acc1[j];
                    }
                }
            }
            __syncthreads();

            if (active && kh == 0) {
#pragma unroll
                for (int j = 0; j < 4; j++) {
                    float2 p0 = sm->red[ridx][lane][j];
                    float2 p1 = sm->red[ridx][lane][j + 4];
                    acc0[j].x += p0.x; acc0[j].y += p0.y;
                    acc1[j].x += p1.x; acc1[j].y += p1.y;
                }
                const int t = s ? (it - 1) : it;
                // unit lu0: batch b0 / b0+1
                {
                    float i_ = sigf(acc0[0].x), f_ = sigf(acc0[0].y);
                    float g_ = tanhx(acc0[1].x), o_ = sigf(acc0[1].y);
                    float cn = f_ * c00 + i_ * g_;
                    float hn = o_ * tanhx(cn);
                    if (t < len0) { c00 = cn; h00 = hn; }
                }
                {
                    float i_ = sigf(acc0[2].x), f_ = sigf(acc0[2].y);
                    float g_ = tanhx(acc0[3].x), o_ = sigf(acc0[3].y);
                    float cn = f_ * c01 + i_ * g_;
                    float hn = o_ * tanhx(cn);
                    if (t < len1) { c01 = cn; h01 = hn; }
                }
                // unit lu0+1
                {
                    float i_ = sigf(acc1[0].x), f_ = sigf(acc1[0].y);
                    float g_ = tanhx(acc1[1].x), o_ = sigf(acc1[1].y);
                    float cn = f_ * c10 + i_ * g_;
                    float hn = o_ * tanhx(cn);
                    if (t < len0) { c10 = cn; h10 = hn; }
                }
                {
                    float i_ = sigf(acc1[2].x), f_ = sigf(acc1[2].y);
                    float g_ = tanhx(acc1[3].x), o_ = sigf(acc1[3].y);
                    float cn = f_ * c11 + i_ * g_;
                    float hn = o_ * tanhx(cn);
                    if (t < len1) { c11 = cn; h11 = hn; }
                }
                float* hout = s ? g_h1[(it + 1) & 1] : g_h0[it & 1];
                int row = (u0 + lu0) * BN + bbase + b0;
                __stcg((float2*)&hout[row],      make_float2(h00, h01));
                __stcg((float2*)&hout[row + BN], make_float2(h10, h11));
            }
            __syncthreads();
            if (tid == 0) {
                __threadfence();
                strel(&g_flag[grp][ub], (unsigned)(it + 1));
            }
        }
    }
    gbar_full();

    // ---- phase 2: LN + FC head (2 batch rows per CTA) ----
    {
        float* hv  = sm->sx;
        float* red = sm->sx + 160;
        const int brow = bid * 2;

        for (int rep = 0; rep < 2; rep++) {
            int b = brow + rep;
            float v = (tid < HN)
                ? __ldcg(&g_h1[(TN - 1) & 1][(size_t)tid * BN + b]) : 0.f;

            float sum = v;
#pragma unroll
            for (int o = 16; o; o >>= 1) sum += __shfl_xor_sync(0xffffffffu, sum, o);
            if ((tid & 31) == 0 && tid < HN) red[tid >> 5] = sum;
            __syncthreads();
            float mu = (red[0] + red[1] + red[2] + red[3]) * (1.0f / HN);

            float d = (tid < HN) ? (v - mu) : 0.f;
            float q = d * d;
#pragma unroll
            for (int o = 16; o; o >>= 1) q += __shfl_xor_sync(0xffffffffu, q, o);
            __syncthreads();
            if ((tid & 31) == 0 && tid < HN) red[tid >> 5] = q;
            __syncthreads();
            float var = (red[0] + red[1] + red[2] + red[3]) * (1.0f / HN);

            if (tid < HN)
                hv[tid] = d * rsqrtf(var + 1e-5f) * a.lng[tid] + a.lnb[tid];
            __syncthreads();

            if (tid < CN) {
                float acc = a.fcb[tid];
#pragma unroll 4
                for (int h = 0; h < HN; h++)
                    acc = fmaf(hv[h], a.fcw[tid * HN + h], acc);
                a.out[b * CN + tid] = acc;
            }
            __syncthreads();
        }
    }
}

// ---------------------------------------------------------------------------
extern "C" void kernel_launch(void* const* d_in, const int* in_sizes, int n_in,
                              void* d_out, int out_size)
{
    LstmArgs a;
    a.x      = (const float*)d_in[0];
    a.length = (const int*)  d_in[1];
    a.Wih0 = (const float*)d_in[2];
    a.Whh0 = (const float*)d_in[3];
    a.bih0 = (const float*)d_in[4];
    a.bhh0 = (const float*)d_in[5];
    a.Wih1 = (const float*)d_in[6];
    a.Whh1 = (const float*)d_in[7];
    a.bih1 = (const float*)d_in[8];
    a.bhh1 = (const float*)d_in[9];
    a.lng  = (const float*)d_in[10];
    a.lnb  = (const float*)d_in[11];
    a.fcw  = (const float*)d_in[12];
    a.fcb  = (const float*)d_in[13];
    a.out  = (float*)d_out;

    static bool attr_done = false;
    if (!attr_done) {
        cudaFuncSetAttribute(lstm_kernel,
                             cudaFuncAttributeMaxDynamicSharedMemorySize,
                             SMEM_BYTES);
        attr_done = true;
    }

    lstm_kernel<<<NCTA, NTHR, SMEM_BYTES>>>(a);
}